// round 3
// baseline (speedup 1.0000x reference)
#include <cuda_runtime.h>
#include <math.h>

// Problem constants
#define NTOK 32768      // 8 * 4096 tokens
#define DIN  1536       // D + DC
#define DH   3072       // 2 * din
#define NE   64         // experts
#define DI   1024       // D
#define DCND 512        // DC

// Scratch for h = gelu(X @ W1^T): 32768 x 3072 fp32 = 402 MB (allowed: __device__ global)
static __device__ float g_h[(size_t)NTOK * DH];

__device__ __forceinline__ float gelu_exact(float x) {
    return 0.5f * x * (1.0f + erff(x * 0.7071067811865475f));
}

// ---------------------------------------------------------------------------
// Kernel 1: g_h[n, m] = gelu( sum_k X[n,k] * W1[m,k] ),  X = concat(inp, cond)
// CTA tile 128 (tokens) x 128 (h cols), K-tile 8, double-buffered smem,
// 8x8 per-thread register tile. Classic fp32 SGEMM.
// ---------------------------------------------------------------------------
__global__ __launch_bounds__(256, 2)
void k_gemm1(const float* __restrict__ inp,
             const float* __restrict__ cnd,
             const float* __restrict__ W1)
{
    __shared__ float As[2][8][132];   // [buf][k][token]   (pad 132 -> conflict-free)
    __shared__ float Bs[2][8][132];   // [buf][k][hcol]

    // Swizzled rasterization: walk the 24 x 256 (mcol x nrow) CTA grid in
    // 2-column bands so resident CTAs share W1 tiles through L2.
    const int ncol = gridDim.x;            // 24
    const int bid  = blockIdx.y * ncol + blockIdx.x;
    const int band = bid / (2 * 256);      // band of 2 columns x 256 rows
    const int rem  = bid % (2 * 256);
    const int mcol = band * 2 + (rem & 1);
    const int nrow = rem >> 1;
    const int mblk = mcol * 128;           // h-column base
    const int nblk = nrow * 128;           // token base

    const int tid  = threadIdx.x;
    const int tx   = tid & 15;           // 0..15 -> 8 h-cols each
    const int ty   = tid >> 4;           // 0..15 -> 8 tokens each
    const int lrow = tid >> 1;           // loader row 0..127
    const int lk4  = (tid & 1) << 2;     // loader k sub-offset 0 or 4

    float acc[8][8];
#pragma unroll
    for (int i = 0; i < 8; i++)
#pragma unroll
        for (int j = 0; j < 8; j++) acc[i][j] = 0.f;

    const size_t arow_i = (size_t)(nblk + lrow) * DI;
    const size_t arow_c = (size_t)(nblk + lrow) * DCND;
    const size_t brow   = (size_t)(mblk + lrow) * DIN;

    float4 av, bv;
    // preload tile k0 = 0 (k < 1024 -> always from inputs)
    av = *(const float4*)(inp + arow_i + lk4);
    bv = *(const float4*)(W1  + brow   + lk4);
    As[0][lk4+0][lrow] = av.x; As[0][lk4+1][lrow] = av.y;
    As[0][lk4+2][lrow] = av.z; As[0][lk4+3][lrow] = av.w;
    Bs[0][lk4+0][lrow] = bv.x; Bs[0][lk4+1][lrow] = bv.y;
    Bs[0][lk4+2][lrow] = bv.z; Bs[0][lk4+3][lrow] = bv.w;
    __syncthreads();

    int buf = 0;
    for (int k0 = 8; k0 <= DIN; k0 += 8) {
        if (k0 < DIN) {
            const int kk = k0 + lk4;
            if (kk < DI) av = *(const float4*)(inp + arow_i + kk);
            else         av = *(const float4*)(cnd + arow_c + (kk - DI));
            bv = *(const float4*)(W1 + brow + kk);
        }
#pragma unroll
        for (int k = 0; k < 8; k++) {
            float4 a0 = *(const float4*)&As[buf][k][ty*8];
            float4 a1 = *(const float4*)&As[buf][k][ty*8+4];
            float4 b0 = *(const float4*)&Bs[buf][k][tx*8];
            float4 b1 = *(const float4*)&Bs[buf][k][tx*8+4];
            float a[8] = {a0.x,a0.y,a0.z,a0.w,a1.x,a1.y,a1.z,a1.w};
            float b[8] = {b0.x,b0.y,b0.z,b0.w,b1.x,b1.y,b1.z,b1.w};
#pragma unroll
            for (int i = 0; i < 8; i++)
#pragma unroll
                for (int j = 0; j < 8; j++)
                    acc[i][j] = fmaf(a[i], b[j], acc[i][j]);
        }
        if (k0 < DIN) {
            const int nb = buf ^ 1;
            As[nb][lk4+0][lrow] = av.x; As[nb][lk4+1][lrow] = av.y;
            As[nb][lk4+2][lrow] = av.z; As[nb][lk4+3][lrow] = av.w;
            Bs[nb][lk4+0][lrow] = bv.x; Bs[nb][lk4+1][lrow] = bv.y;
            Bs[nb][lk4+2][lrow] = bv.z; Bs[nb][lk4+3][lrow] = bv.w;
            buf = nb;
        }
        __syncthreads();
    }

    // epilogue: GELU + store to scratch
#pragma unroll
    for (int i = 0; i < 8; i++) {
        const int n = nblk + ty*8 + i;
        float* dst = g_h + (size_t)n * DH + mblk + tx*8;
        float4 o0, o1;
        o0.x = gelu_exact(acc[i][0]); o0.y = gelu_exact(acc[i][1]);
        o0.z = gelu_exact(acc[i][2]); o0.w = gelu_exact(acc[i][3]);
        o1.x = gelu_exact(acc[i][4]); o1.y = gelu_exact(acc[i][5]);
        o1.z = gelu_exact(acc[i][6]); o1.w = gelu_exact(acc[i][7]);
        *(float4*)(dst)     = o0;
        *(float4*)(dst + 4) = o1;
    }
}

// ---------------------------------------------------------------------------
// Kernel 2: logits[n,e] = sum_k h[n,k] * W2[e,k], then softmax + top-2 + outputs.
// CTA tile 128 (tokens) x 64 (experts), K-tile 8, double-buffered.
// 8x4 per-thread tile. Fused epilogue: 1 thread per row over 64 experts.
// ---------------------------------------------------------------------------
__global__ __launch_bounds__(256, 2)
void k_gemm2(const float* __restrict__ W2, float* __restrict__ out)
{
    __shared__ float As[2][8][132];   // [buf][k][token]
    __shared__ float Bs[2][8][68];    // [buf][k][expert]
    __shared__ float lg[128][65];     // logits staging

    const int nblk = blockIdx.x * 128;
    const int tid  = threadIdx.x;
    const int tx   = tid & 15;        // 0..15 -> 4 experts each
    const int ty   = tid >> 4;        // 0..15 -> 8 tokens each
    const int lrow = tid >> 1;        // A-loader row 0..127
    const int lk4  = (tid & 1) << 2;  // 0 or 4

    float acc[8][4];
#pragma unroll
    for (int i = 0; i < 8; i++)
#pragma unroll
        for (int j = 0; j < 4; j++) acc[i][j] = 0.f;

    const size_t arow = (size_t)(nblk + lrow) * DH;
    const int    erow = tid >> 1;               // B-loader expert 0..63 (tid<128)
    const size_t brow = (size_t)erow * DH;

    float4 av, bv;
    av = *(const float4*)(g_h + arow + lk4);
    if (tid < 128) bv = *(const float4*)(W2 + brow + lk4);
    As[0][lk4+0][lrow] = av.x; As[0][lk4+1][lrow] = av.y;
    As[0][lk4+2][lrow] = av.z; As[0][lk4+3][lrow] = av.w;
    if (tid < 128) {
        Bs[0][lk4+0][erow] = bv.x; Bs[0][lk4+1][erow] = bv.y;
        Bs[0][lk4+2][erow] = bv.z; Bs[0][lk4+3][erow] = bv.w;
    }
    __syncthreads();

    int buf = 0;
    for (int k0 = 8; k0 <= DH; k0 += 8) {
        if (k0 < DH) {
            av = *(const float4*)(g_h + arow + k0 + lk4);
            if (tid < 128) bv = *(const float4*)(W2 + brow + k0 + lk4);
        }
#pragma unroll
        for (int k = 0; k < 8; k++) {
            float4 a0 = *(const float4*)&As[buf][k][ty*8];
            float4 a1 = *(const float4*)&As[buf][k][ty*8+4];
            float4 b0 = *(const float4*)&Bs[buf][k][tx*4];
            float a[8] = {a0.x,a0.y,a0.z,a0.w,a1.x,a1.y,a1.z,a1.w};
            float b[4] = {b0.x,b0.y,b0.z,b0.w};
#pragma unroll
            for (int i = 0; i < 8; i++)
#pragma unroll
                for (int j = 0; j < 4; j++)
                    acc[i][j] = fmaf(a[i], b[j], acc[i][j]);
        }
        if (k0 < DH) {
            const int nb = buf ^ 1;
            As[nb][lk4+0][lrow] = av.x; As[nb][lk4+1][lrow] = av.y;
            As[nb][lk4+2][lrow] = av.z; As[nb][lk4+3][lrow] = av.w;
            if (tid < 128) {
                Bs[nb][lk4+0][erow] = bv.x; Bs[nb][lk4+1][erow] = bv.y;
                Bs[nb][lk4+2][erow] = bv.z; Bs[nb][lk4+3][erow] = bv.w;
            }
            buf = nb;
        }
        __syncthreads();
    }

    // stage logits to smem
#pragma unroll
    for (int i = 0; i < 8; i++)
#pragma unroll
        for (int j = 0; j < 4; j++)
            lg[ty*8+i][tx*4+j] = acc[i][j];
    __syncthreads();

    // per-row softmax + top-2 + all four outputs
    if (tid < 128) {
        const int r = tid;
        const int n = nblk + r;

        float m1 = -1e30f; int i1 = 0;
#pragma unroll
        for (int e = 0; e < NE; e++) {
            float v = lg[r][e];
            if (v > m1) { m1 = v; i1 = e; }
        }
        float m2 = -1e30f; int i2 = 0;
#pragma unroll
        for (int e = 0; e < NE; e++) {
            if (e == i1) continue;
            float v = lg[r][e];
            if (v > m2) { m2 = v; i2 = e; }
        }
        float s = 0.f;
#pragma unroll
        for (int e = 0; e < NE; e++) s += expf(lg[r][e] - m1);
        const float inv = 1.0f / s;

        const float lo = 1e-9f, hi = 1.0f - 1e-9f;
        const float p1 = fminf(fmaxf(inv + lo, lo), hi);                 // exp(0)*inv + eps
        const float p2 = fminf(fmaxf(expf(m2 - m1) * inv + lo, lo), hi);
        const float rn = 1.0f / (p1 + p2);

        // output layout (concatenated, return order, all fp32):
        float* mask = out;                                         // [N,64]
        float* ti   = out + (size_t)NTOK * NE;                     // [N,2]
        float* rp   = out + (size_t)NTOK * NE + (size_t)NTOK * 2;  // [N,64]
        float* pr   = rp  + (size_t)NTOK * NE;                     // [N,64]

#pragma unroll
        for (int e = 0; e < NE; e++) {
            float v = expf(lg[r][e] - m1) * inv + lo;
            v = fminf(fmaxf(v, lo), hi);
            pr[(size_t)n * NE + e]   = v;
            mask[(size_t)n * NE + e] = (e == i1 || e == i2) ? 1.0f : 0.0f;
            rp[(size_t)n * NE + e]   = (e == i1) ? p1 * rn
                                     : (e == i2) ? p2 * rn : 0.0f;
        }
        ti[(size_t)n * 2 + 0] = (float)i1;
        ti[(size_t)n * 2 + 1] = (float)i2;
    }
}

// ---------------------------------------------------------------------------
extern "C" void kernel_launch(void* const* d_in, const int* in_sizes, int n_in,
                              void* d_out, int out_size)
{
    const float* inp = (const float*)d_in[0];   // [8,4096,1024]
    const float* cnd = (const float*)d_in[1];   // [8,4096,512]
    const float* W1  = (const float*)d_in[2];   // [3072,1536]
    const float* W2  = (const float*)d_in[3];   // [64,3072]
    float* out = (float*)d_out;

    dim3 g1(DH / 128, NTOK / 128);   // 24 x 256 CTAs
    k_gemm1<<<g1, 256>>>(inp, cnd, W1);
    k_gemm2<<<NTOK / 128, 256>>>(W2, out);
}

// round 6
// speedup vs baseline: 1.4424x; 1.4424x over previous
#include <cuda_runtime.h>
#include <math.h>
#include <stdint.h>

// Problem constants
#define NTOK 32768      // 8 * 4096 tokens
#define DIN  1536       // D + DC
#define DH   3072       // 2 * din
#define NE   64         // experts
#define DI   1024       // D
#define DCND 512        // DC

// GEMM1 mma.sync tiling: CTA 128 tokens x 128 hcols, K-chunk 32
#define KC     32
#define NCHUNK (DIN / KC)        // 48
#define SSTR   36                // smem row stride (floats): bank = 4*row+col, conflict-free
#define A_HI   0
#define A_LO   (128 * SSTR)      // 4608
#define B_HI   (2 * 128 * SSTR)  // 9216
#define B_LO   (3 * 128 * SSTR)  // 13824
#define STG    (4 * 128 * SSTR)  // 18432 floats per stage
#define SMEM1_BYTES (2 * STG * 4)  // 147456 B

// Scratch for h = gelu(X @ W1^T): 32768 x 3072 fp32 = 402 MB
static __device__ float g_h[(size_t)NTOK * DH];

__device__ __forceinline__ float gelu_exact(float x) {
    return 0.5f * x * (1.0f + erff(x * 0.7071067811865475f));
}

// Round to tf32 (RNA), return hi and tf32-rounded residual lo.
__device__ __forceinline__ void tf32_split(float x, float& h, float& l) {
    uint32_t t;
    asm("cvt.rna.tf32.f32 %0, %1;" : "=r"(t) : "f"(x));
    h = __uint_as_float(t);
    float r = x - h;                      // exact in fp32
    asm("cvt.rna.tf32.f32 %0, %1;" : "=r"(t) : "f"(r));
    l = __uint_as_float(t);
}

__device__ __forceinline__ void mma1688(float c[4], const uint32_t a[4], const uint32_t b[2]) {
    asm volatile(
        "mma.sync.aligned.m16n8k8.row.col.f32.tf32.tf32.f32 "
        "{%0,%1,%2,%3}, {%4,%5,%6,%7}, {%8,%9}, {%0,%1,%2,%3};"
        : "+f"(c[0]), "+f"(c[1]), "+f"(c[2]), "+f"(c[3])
        : "r"(a[0]), "r"(a[1]), "r"(a[2]), "r"(a[3]), "r"(b[0]), "r"(b[1]));
}

// ---------------------------------------------------------------------------
// GEMM1 (mma.sync tf32, 3xTF32 split): g_h[n,m] = gelu( X[n,:] . W1[m,:] )
// ---------------------------------------------------------------------------
extern "C" __global__ void __launch_bounds__(256)
k_gemm1_mma(const float* __restrict__ inp,
            const float* __restrict__ cnd,
            const float* __restrict__ W1)
{
    extern __shared__ float sm[];

    const int tid  = threadIdx.x;
    const int lane = tid & 31;
    const int wid  = tid >> 5;
    const int wm   = wid & 1;          // 0..1 : 64-token half
    const int wn   = wid >> 1;         // 0..3 : 32-hcol slice
    const int gID  = lane >> 2;        // 0..7
    const int tig  = lane & 3;         // 0..3
    const int mblk = blockIdx.x * 128; // hcol base
    const int nblk = blockIdx.y * 128; // token base

    // loader mapping: 1024 float4 per matrix per chunk -> 4/thread
    const int lrow = tid >> 3;         // would cover 32 rows/iter; use idx scheme below

    float acc[4][4][4];
#pragma unroll
    for (int mt = 0; mt < 4; mt++)
#pragma unroll
        for (int nt = 0; nt < 4; nt++)
#pragma unroll
            for (int q = 0; q < 4; q++) acc[mt][nt][q] = 0.f;

    float4 pa[4], pb[4];

    // ---- helpers as lambdas ----
    auto load_chunk = [&](int c) {
        const int kbase = c * KC;
#pragma unroll
        for (int it = 0; it < 4; ++it) {
            const int idx = tid + it * 256;
            const int row = idx >> 3, c4 = idx & 7;
            const int kk = kbase + c4 * 4;
            const float* asrc = (kk < DI)
                ? inp + (size_t)(nblk + row) * DI   + kk
                : cnd + (size_t)(nblk + row) * DCND + (kk - DI);
            pa[it] = *(const float4*)asrc;
            pb[it] = *(const float4*)(W1 + (size_t)(mblk + row) * DIN + kk);
        }
    };
    auto store_chunk = [&](int buf) {
        float* st = sm + buf * STG;
#pragma unroll
        for (int it = 0; it < 4; ++it) {
            const int idx = tid + it * 256;
            const int row = idx >> 3, c4 = idx & 7;
            const int off = row * SSTR + c4 * 4;
            float4 h, l;
            tf32_split(pa[it].x, h.x, l.x); tf32_split(pa[it].y, h.y, l.y);
            tf32_split(pa[it].z, h.z, l.z); tf32_split(pa[it].w, h.w, l.w);
            *(float4*)(st + A_HI + off) = h;
            *(float4*)(st + A_LO + off) = l;
            tf32_split(pb[it].x, h.x, l.x); tf32_split(pb[it].y, h.y, l.y);
            tf32_split(pb[it].z, h.z, l.z); tf32_split(pb[it].w, h.w, l.w);
            *(float4*)(st + B_HI + off) = h;
            *(float4*)(st + B_LO + off) = l;
        }
    };

    // prologue: chunk 0 -> stage 0
    load_chunk(0);
    store_chunk(0);
    __syncthreads();

    for (int c = 0; c < NCHUNK; ++c) {
        const int buf = c & 1;
        const bool more = (c + 1) < NCHUNK;
        if (more) load_chunk(c + 1);

        const uint32_t* Ah = (const uint32_t*)(sm + buf * STG + A_HI);
        const uint32_t* Al = (const uint32_t*)(sm + buf * STG + A_LO);
        const uint32_t* Bh = (const uint32_t*)(sm + buf * STG + B_HI);
        const uint32_t* Bl = (const uint32_t*)(sm + buf * STG + B_LO);

#pragma unroll
        for (int ks = 0; ks < 4; ++ks) {
            const int kb = ks * 8;
            uint32_t ahi[4][4], alo[4][4], bhi[4][2], blo[4][2];
#pragma unroll
            for (int mt = 0; mt < 4; ++mt) {
                const int r0 = (wm * 64 + mt * 16 + gID) * SSTR + kb + tig;
                const int r1 = r0 + 8 * SSTR;
                ahi[mt][0] = Ah[r0];     ahi[mt][1] = Ah[r1];
                ahi[mt][2] = Ah[r0 + 4]; ahi[mt][3] = Ah[r1 + 4];
                alo[mt][0] = Al[r0];     alo[mt][1] = Al[r1];
                alo[mt][2] = Al[r0 + 4]; alo[mt][3] = Al[r1 + 4];
            }
#pragma unroll
            for (int nt = 0; nt < 4; ++nt) {
                const int r0 = (wn * 32 + nt * 8 + gID) * SSTR + kb + tig;
                bhi[nt][0] = Bh[r0]; bhi[nt][1] = Bh[r0 + 4];
                blo[nt][0] = Bl[r0]; blo[nt][1] = Bl[r0 + 4];
            }
#pragma unroll
            for (int mt = 0; mt < 4; ++mt)
#pragma unroll
                for (int nt = 0; nt < 4; ++nt) {
                    mma1688(acc[mt][nt], ahi[mt], bhi[nt]);
                    mma1688(acc[mt][nt], ahi[mt], blo[nt]);
                    mma1688(acc[mt][nt], alo[mt], bhi[nt]);
                }
        }

        if (more) store_chunk((c + 1) & 1);
        __syncthreads();
    }

    // ---- epilogue: GELU + store to g_h ----
#pragma unroll
    for (int mt = 0; mt < 4; ++mt) {
        const int row0 = nblk + wm * 64 + mt * 16 + gID;
#pragma unroll
        for (int nt = 0; nt < 4; ++nt) {
            const int col = mblk + wn * 32 + nt * 8 + tig * 2;
            float2 v0, v1;
            v0.x = gelu_exact(acc[mt][nt][0]);
            v0.y = gelu_exact(acc[mt][nt][1]);
            v1.x = gelu_exact(acc[mt][nt][2]);
            v1.y = gelu_exact(acc[mt][nt][3]);
            *(float2*)(g_h + (size_t)row0 * DH + col)       = v0;
            *(float2*)(g_h + (size_t)(row0 + 8) * DH + col) = v1;
        }
    }
    (void)lrow;
}

// ---------------------------------------------------------------------------
// Kernel 2 (unchanged, passing): logits + softmax + top-2 + outputs
// ---------------------------------------------------------------------------
__global__ __launch_bounds__(256, 2)
void k_gemm2(const float* __restrict__ W2, float* __restrict__ out)
{
    __shared__ float As[2][8][132];
    __shared__ float Bs[2][8][68];
    __shared__ float lg[128][65];

    const int nblk = blockIdx.x * 128;
    const int tid  = threadIdx.x;
    const int tx   = tid & 15;
    const int ty   = tid >> 4;
    const int lrow = tid >> 1;
    const int lk4  = (tid & 1) << 2;

    float acc[8][4];
#pragma unroll
    for (int i = 0; i < 8; i++)
#pragma unroll
        for (int j = 0; j < 4; j++) acc[i][j] = 0.f;

    const size_t arow = (size_t)(nblk + lrow) * DH;
    const int    erow = tid >> 1;
    const size_t brow = (size_t)erow * DH;

    float4 av, bv;
    av = *(const float4*)(g_h + arow + lk4);
    if (tid < 128) bv = *(const float4*)(W2 + brow + lk4);
    As[0][lk4+0][lrow] = av.x; As[0][lk4+1][lrow] = av.y;
    As[0][lk4+2][lrow] = av.z; As[0][lk4+3][lrow] = av.w;
    if (tid < 128) {
        Bs[0][lk4+0][erow] = bv.x; Bs[0][lk4+1][erow] = bv.y;
        Bs[0][lk4+2][erow] = bv.z; Bs[0][lk4+3][erow] = bv.w;
    }
    __syncthreads();

    int buf = 0;
    for (int k0 = 8; k0 <= DH; k0 += 8) {
        if (k0 < DH) {
            av = *(const float4*)(g_h + arow + k0 + lk4);
            if (tid < 128) bv = *(const float4*)(W2 + brow + k0 + lk4);
        }
#pragma unroll
        for (int k = 0; k < 8; k++) {
            float4 a0 = *(const float4*)&As[buf][k][ty*8];
            float4 a1 = *(const float4*)&As[buf][k][ty*8+4];
            float4 b0 = *(const float4*)&Bs[buf][k][tx*4];
            float a[8] = {a0.x,a0.y,a0.z,a0.w,a1.x,a1.y,a1.z,a1.w};
            float b[4] = {b0.x,b0.y,b0.z,b0.w};
#pragma unroll
            for (int i = 0; i < 8; i++)
#pragma unroll
                for (int j = 0; j < 4; j++)
                    acc[i][j] = fmaf(a[i], b[j], acc[i][j]);
        }
        if (k0 < DH) {
            const int nb = buf ^ 1;
            As[nb][lk4+0][lrow] = av.x; As[nb][lk4+1][lrow] = av.y;
            As[nb][lk4+2][lrow] = av.z; As[nb][lk4+3][lrow] = av.w;
            if (tid < 128) {
                Bs[nb][lk4+0][erow] = bv.x; Bs[nb][lk4+1][erow] = bv.y;
                Bs[nb][lk4+2][erow] = bv.z; Bs[nb][lk4+3][erow] = bv.w;
            }
            buf = nb;
        }
        __syncthreads();
    }

#pragma unroll
    for (int i = 0; i < 8; i++)
#pragma unroll
        for (int j = 0; j < 4; j++)
            lg[ty*8+i][tx*4+j] = acc[i][j];
    __syncthreads();

    if (tid < 128) {
        const int r = tid;
        const int n = nblk + r;

        float m1 = -1e30f; int i1 = 0;
#pragma unroll
        for (int e = 0; e < NE; e++) {
            float v = lg[r][e];
            if (v > m1) { m1 = v; i1 = e; }
        }
        float m2 = -1e30f; int i2 = 0;
#pragma unroll
        for (int e = 0; e < NE; e++) {
            if (e == i1) continue;
            float v = lg[r][e];
            if (v > m2) { m2 = v; i2 = e; }
        }
        float s = 0.f;
#pragma unroll
        for (int e = 0; e < NE; e++) s += expf(lg[r][e] - m1);
        const float inv = 1.0f / s;

        const float lo = 1e-9f, hi = 1.0f - 1e-9f;
        const float p1 = fminf(fmaxf(inv + lo, lo), hi);
        const float p2 = fminf(fmaxf(expf(m2 - m1) * inv + lo, lo), hi);
        const float rn = 1.0f / (p1 + p2);

        float* mask = out;
        float* ti   = out + (size_t)NTOK * NE;
        float* rp   = out + (size_t)NTOK * NE + (size_t)NTOK * 2;
        float* pr   = rp  + (size_t)NTOK * NE;

#pragma unroll
        for (int e = 0; e < NE; e++) {
            float v = expf(lg[r][e] - m1) * inv + lo;
            v = fminf(fmaxf(v, lo), hi);
            pr[(size_t)n * NE + e]   = v;
            mask[(size_t)n * NE + e] = (e == i1 || e == i2) ? 1.0f : 0.0f;
            rp[(size_t)n * NE + e]   = (e == i1) ? p1 * rn
                                     : (e == i2) ? p2 * rn : 0.0f;
        }
        ti[(size_t)n * 2 + 0] = (float)i1;
        ti[(size_t)n * 2 + 1] = (float)i2;
    }
}

// ---------------------------------------------------------------------------
extern "C" void kernel_launch(void* const* d_in, const int* in_sizes, int n_in,
                              void* d_out, int out_size)
{
    const float* inp = (const float*)d_in[0];   // [8,4096,1024]
    const float* cnd = (const float*)d_in[1];   // [8,4096,512]
    const float* W1  = (const float*)d_in[2];   // [3072,1536]
    const float* W2  = (const float*)d_in[3];   // [64,3072]
    float* out = (float*)d_out;

    cudaFuncSetAttribute(k_gemm1_mma, cudaFuncAttributeMaxDynamicSharedMemorySize, SMEM1_BYTES);

    dim3 g1(DH / 128, NTOK / 128);   // 24 x 256 CTAs
    k_gemm1_mma<<<g1, 256, SMEM1_BYTES>>>(inp, cnd, W1);
    k_gemm2<<<NTOK / 128, 256>>>(W2, out);
}